// round 5
// baseline (speedup 1.0000x reference)
#include <cuda_runtime.h>
#include <math.h>

#define N_PTS 8192
#define M_PTS 2048
#define K_LAST 10
#define VARS 3

typedef unsigned long long u64;

// ---------------- packed f32x2 helpers (sm_100+) ----------------
__device__ __forceinline__ u64 pk2(float lo, float hi) {
    u64 r; asm("mov.b64 %0,{%1,%2};" : "=l"(r) : "f"(lo), "f"(hi)); return r;
}
__device__ __forceinline__ u64 dup2(float x) { return pk2(x, x); }
__device__ __forceinline__ void unpk2(u64 v, float& lo, float& hi) {
    asm("mov.b64 {%0,%1},%2;" : "=f"(lo), "=f"(hi) : "l"(v));
}
__device__ __forceinline__ u64 f2fma(u64 a, u64 b, u64 c) {
    u64 d; asm("fma.rn.f32x2 %0,%1,%2,%3;" : "=l"(d) : "l"(a), "l"(b), "l"(c)); return d;
}
__device__ __forceinline__ u64 f2mul(u64 a, u64 b) {
    u64 d; asm("mul.rn.f32x2 %0,%1,%2;" : "=l"(d) : "l"(a), "l"(b)); return d;
}

// scalar exact GELU for proj kernel
__device__ __forceinline__ float gelu(float x) {
    return 0.5f * x * (1.0f + erff(x * 0.70710678118654752f));
}

// packed GELU via Abramowitz-Stegun 7.1.26 erf (abs err <= 1.5e-7), branchless
__device__ __forceinline__ u64 gelu2(u64 x) {
    u64 ax = x & 0x7FFFFFFF7FFFFFFFULL;
    u64 z  = f2mul(ax, dup2(0.70710678118654752f));
    u64 den = f2fma(z, dup2(0.3275911f), dup2(1.0f));
    float dl, dh, rl, rh;
    unpk2(den, dl, dh);
    asm("rcp.approx.f32 %0,%1;" : "=f"(rl) : "f"(dl));
    asm("rcp.approx.f32 %0,%1;" : "=f"(rh) : "f"(dh));
    u64 t = pk2(rl, rh);
    u64 z2 = f2mul(z, z);
    u64 m  = f2mul(z2, dup2(-1.4426950408889634f));
    float ml, mh, el, eh;
    unpk2(m, ml, mh);
    asm("ex2.approx.f32 %0,%1;" : "=f"(el) : "f"(ml));
    asm("ex2.approx.f32 %0,%1;" : "=f"(eh) : "f"(mh));
    u64 e = pk2(el, eh);
    u64 p = f2fma(t, dup2(1.061405429f), dup2(-1.453152027f));
    p = f2fma(p, t, dup2(1.421413741f));
    p = f2fma(p, t, dup2(-0.284496736f));
    p = f2fma(p, t, dup2(0.254829592f));
    p = f2mul(p, t);
    u64 np = p ^ 0x8000000080000000ULL;
    u64 u  = f2fma(np, e, dup2(1.0f));
    u64 E  = u | (x & 0x8000000080000000ULL);
    u64 h  = f2fma(E, dup2(0.5f), dup2(0.5f));
    return f2mul(x, h);
}

// scratch
__device__ float g_f0[VARS * N_PTS * 32];
__device__ float g_acc[VARS * N_PTS * 32];

// ---------------------------------------------------------------------------
// Projection MLP: per (var,point): 8 -> gelu 64 -> 32. One warp per (var,pt).
// ---------------------------------------------------------------------------
__global__ void proj_kernel(const float* __restrict__ inp,
                            const float* __restrict__ W0, const float* __restrict__ b0,
                            const float* __restrict__ W1, const float* __restrict__ b1,
                            float* __restrict__ f0) {
    __shared__ float hs[4][64];
    int warp = threadIdx.x >> 5, lane = threadIdx.x & 31;
    int pv = blockIdx.x * 4 + warp;
    if (pv >= VARS * N_PTS) return;
    int v = pv / N_PTS, n = pv - v * N_PTS;
    const float* x = inp + n * (VARS * 8) + v * 8;
    float xr[8];
#pragma unroll
    for (int i = 0; i < 8; i++) xr[i] = x[i];
    float a0 = b0[lane], a1 = b0[lane + 32];
#pragma unroll
    for (int i = 0; i < 8; i++) {
        a0 = fmaf(xr[i], W0[i * 64 + lane], a0);
        a1 = fmaf(xr[i], W0[i * 64 + lane + 32], a1);
    }
    hs[warp][lane]      = gelu(a0);
    hs[warp][lane + 32] = gelu(a1);
    __syncwarp();
    float acc = b1[lane];
#pragma unroll
    for (int h = 0; h < 64; h++) acc = fmaf(hs[warp][h], W1[h * 32 + lane], acc);
    f0[(size_t)pv * 32 + lane] = acc;
}

// ---------------------------------------------------------------------------
// Edge MLP 36->80(gelu)->80(gelu)->32. One edge per thread; h1 lives in
// REGISTERS (40 u64 packed pairs). Inputs staged per-thread in shared with
// stride 37 (conflict-free scalar LDS in the rolled layer-1 loop). Weights
// in shared, all reads LDS.128. 67KB smem/block -> 3 blocks x 4 warps / SM.
// ---------------------------------------------------------------------------
#define TPB 128
#define X_STRIDE 37

template <int MODE>
__global__ void __launch_bounds__(TPB, 3)
edge_kernel(const float* __restrict__ Wa, const float* __restrict__ ba,
            const float* __restrict__ Wb, const float* __restrict__ bb,
            const float* __restrict__ Wc, const float* __restrict__ bc,
            const float* __restrict__ grid_in, const float* __restrict__ grid_out,
            const float* __restrict__ fsrc,
            const int* __restrict__ idxA, const int* __restrict__ idxB,
            float* __restrict__ outbuf, int E) {
    extern __shared__ float sm[];
    float* W0s = sm;            // [36][80]  2880
    float* W1s = W0s + 2880;    // [80][80]  6400
    float* W2s = W1s + 6400;    // [80][32]  2560
    float* b0s = W2s + 2560;    // 80
    float* b1s = b0s + 80;      // 80
    float* b2s = b1s + 80;      // 32
    float* xs  = sm + 12032;    // TPB * 37 input stage

    int tid = threadIdx.x;
    for (int i = tid; i < 2880; i += TPB) W0s[i] = Wa[i];
    for (int i = tid; i < 6400; i += TPB) W1s[i] = Wb[i];
    for (int i = tid; i < 2560; i += TPB) W2s[i] = Wc[i];
    if (tid < 80) { b0s[tid] = ba[tid]; b1s[tid] = bb[tid]; }
    if (tid < 32) b2s[tid] = bc[tid];

    int v = blockIdx.y;
    int e = blockIdx.x * TPB + tid;
    bool valid = e < E;
    if (!valid) e = 0;
    int jn = idxA[e];
    int segd = (MODE == 0) ? idxB[e] : e / K_LAST;

    // ---- gather input [pos_nbr(2), pos_self(2), f[nbr](32)] into smem stage ----
    float* myx = xs + tid * X_STRIDE;
    if (MODE == 0) {
        myx[0] = grid_in[2 * jn];   myx[1] = grid_in[2 * jn + 1];
        myx[2] = grid_in[2 * segd]; myx[3] = grid_in[2 * segd + 1];
    } else {
        myx[0] = grid_in[2 * jn];    myx[1] = grid_in[2 * jn + 1];
        myx[2] = grid_out[2 * segd]; myx[3] = grid_out[2 * segd + 1];
    }
    {
        const float4* fpv = (const float4*)(fsrc + ((size_t)v * N_PTS + jn) * 32);
#pragma unroll
        for (int q = 0; q < 8; q++) {
            float4 t = fpv[q];
            myx[4 + 4 * q] = t.x; myx[5 + 4 * q] = t.y;
            myx[6 + 4 * q] = t.z; myx[7 + 4 * q] = t.w;
        }
    }
    __syncthreads();

    // ---- layer 1: 36 -> 80, all 40 packed accumulators in registers ----
    u64 h[40];
    {
        const ulonglong2* bv = (const ulonglong2*)b0s;
#pragma unroll
        for (int q = 0; q < 20; q++) { ulonglong2 t = bv[q]; h[2*q] = t.x; h[2*q+1] = t.y; }
    }
#pragma unroll 1
    for (int i = 0; i < 36; i++) {
        u64 xi = dup2(myx[i]);
        const ulonglong2* w = (const ulonglong2*)(W0s + i * 80);
#pragma unroll
        for (int q = 0; q < 20; q++) {
            ulonglong2 t = w[q];
            h[2*q]   = f2fma(xi, t.x, h[2*q]);
            h[2*q+1] = f2fma(xi, t.y, h[2*q+1]);
        }
    }
#pragma unroll
    for (int q = 0; q < 40; q++) h[q] = gelu2(h[q]);

    // ---- layers 2+3 fused: 80 -> 80(gelu) streamed into 80 -> 32 ----
    u64 out[16];
    {
        const ulonglong2* bv = (const ulonglong2*)b2s;
#pragma unroll
        for (int q = 0; q < 8; q++) { ulonglong2 t = bv[q]; out[2*q] = t.x; out[2*q+1] = t.y; }
    }

#pragma unroll 1
    for (int jt = 0; jt < 10; jt++) {
        ulonglong2 bv0 = ((const ulonglong2*)(b1s + jt * 8))[0];
        ulonglong2 bv1 = ((const ulonglong2*)(b1s + jt * 8))[1];
        u64 a0 = bv0.x, a1 = bv0.y, a2 = bv1.x, a3 = bv1.y;
        const float* wb1 = W1s + jt * 8;
#pragma unroll
        for (int kq = 0; kq < 20; kq++) {      // k = 4*kq .. 4*kq+3
            float h0, h1v, h2, h3;
            unpk2(h[2*kq],   h0, h1v);
            unpk2(h[2*kq+1], h2, h3);
            u64 d0 = dup2(h0), d1 = dup2(h1v), d2 = dup2(h2), d3 = dup2(h3);
            const float* wr = wb1 + (4 * kq) * 80;
            ulonglong2 wA0 = *(const ulonglong2*)(wr);
            ulonglong2 wB0 = *(const ulonglong2*)(wr + 4);
            ulonglong2 wA1 = *(const ulonglong2*)(wr + 80);
            ulonglong2 wB1 = *(const ulonglong2*)(wr + 84);
            ulonglong2 wA2 = *(const ulonglong2*)(wr + 160);
            ulonglong2 wB2 = *(const ulonglong2*)(wr + 164);
            ulonglong2 wA3 = *(const ulonglong2*)(wr + 240);
            ulonglong2 wB3 = *(const ulonglong2*)(wr + 244);
            a0 = f2fma(d0, wA0.x, a0); a1 = f2fma(d0, wA0.y, a1);
            a2 = f2fma(d0, wB0.x, a2); a3 = f2fma(d0, wB0.y, a3);
            a0 = f2fma(d1, wA1.x, a0); a1 = f2fma(d1, wA1.y, a1);
            a2 = f2fma(d1, wB1.x, a2); a3 = f2fma(d1, wB1.y, a3);
            a0 = f2fma(d2, wA2.x, a0); a1 = f2fma(d2, wA2.y, a1);
            a2 = f2fma(d2, wB2.x, a2); a3 = f2fma(d2, wB2.y, a3);
            a0 = f2fma(d3, wA3.x, a0); a1 = f2fma(d3, wA3.y, a1);
            a2 = f2fma(d3, wB3.x, a2); a3 = f2fma(d3, wB3.y, a3);
        }
        u64 av[4] = { a0, a1, a2, a3 };
#pragma unroll
        for (int q = 0; q < 4; q++) {
            u64 g = gelu2(av[q]);
            float g0, g1; unpk2(g, g0, g1);
            u64 gd0 = dup2(g0), gd1 = dup2(g1);
            const ulonglong2* w2a = (const ulonglong2*)(W2s + (jt * 8 + 2 * q) * 32);
            const ulonglong2* w2b = (const ulonglong2*)(W2s + (jt * 8 + 2 * q + 1) * 32);
#pragma unroll
            for (int o = 0; o < 8; o++) {
                ulonglong2 wa = w2a[o];
                ulonglong2 wbv = w2b[o];
                out[2*o]   = f2fma(gd0, wa.x,  out[2*o]);
                out[2*o+1] = f2fma(gd0, wa.y,  out[2*o+1]);
                out[2*o]   = f2fma(gd1, wbv.x, out[2*o]);
                out[2*o+1] = f2fma(gd1, wbv.y, out[2*o+1]);
            }
        }
    }

    // ---- scatter ----
    if (valid) {
        float* dst; float scale;
        if (MODE == 0) { dst = outbuf + ((size_t)v * N_PTS + segd) * 32; scale = 1.0f; }
        else           { dst = outbuf + (size_t)segd * (VARS * 32) + v * 32; scale = 0.1f; }
#pragma unroll
        for (int q = 0; q < 16; q++) {
            float a, b; unpk2(out[q], a, b);
            atomicAdd(dst + 2 * q,     a * scale);
            atomicAdd(dst + 2 * q + 1, b * scale);
        }
    }
}

// f1 = segment_sum * inv_count + f0 (in place into f0)
__global__ void f1_kernel(float* __restrict__ f0, const float* __restrict__ acc,
                          const int* __restrict__ counts) {
    int idx = blockIdx.x * 256 + threadIdx.x;
    if (idx >= VARS * N_PTS * 32) return;
    int n = (idx >> 5) % N_PTS;
    int c = counts[n];
    float inv = 1.0f / (float)(c > 1 ? c : 1);
    f0[idx] = fmaf(acc[idx], inv, f0[idx]);
}

extern "C" void kernel_launch(void* const* d_in, const int* in_sizes, int n_in,
                              void* d_out, int out_size) {
    const float* inp   = (const float*)d_in[0];
    const float* gin   = (const float*)d_in[1];
    const float* gout  = (const float*)d_in[2];
    const float* pW0   = (const float*)d_in[3];
    const float* pb0   = (const float*)d_in[4];
    const float* pW1   = (const float*)d_in[5];
    const float* pb1   = (const float*)d_in[6];
    const float* i0W0  = (const float*)d_in[7];
    const float* i0b0  = (const float*)d_in[8];
    const float* i0W1  = (const float*)d_in[9];
    const float* i0b1  = (const float*)d_in[10];
    const float* i0W2  = (const float*)d_in[11];
    const float* i0b2  = (const float*)d_in[12];
    const float* i1W0  = (const float*)d_in[13];
    const float* i1b0  = (const float*)d_in[14];
    const float* i1W1  = (const float*)d_in[15];
    const float* i1b1  = (const float*)d_in[16];
    const float* i1W2  = (const float*)d_in[17];
    const float* i1b2  = (const float*)d_in[18];
    const int* nbr_index  = (const int*)d_in[19];
    const int* nbr_seg    = (const int*)d_in[20];
    const int* nbr_counts = (const int*)d_in[21];
    const int* nbr_last   = (const int*)d_in[22];
    int E = in_sizes[19];

    float *f0, *acc;
    cudaGetSymbolAddress((void**)&f0,  g_f0);
    cudaGetSymbolAddress((void**)&acc, g_acc);

    cudaMemsetAsync(acc, 0, sizeof(float) * VARS * N_PTS * 32);
    cudaMemsetAsync(d_out, 0, sizeof(float) * (size_t)out_size);

    proj_kernel<<<(VARS * N_PTS + 3) / 4, 128>>>(inp, pW0, pb0, pW1, pb1, f0);

    const int SMEM = (12032 + TPB * X_STRIDE) * (int)sizeof(float);  // 67,072 B
    cudaFuncSetAttribute(edge_kernel<0>, cudaFuncAttributeMaxDynamicSharedMemorySize, SMEM);
    cudaFuncSetAttribute(edge_kernel<1>, cudaFuncAttributeMaxDynamicSharedMemorySize, SMEM);

    dim3 g1((unsigned)((E + TPB - 1) / TPB), VARS);
    edge_kernel<0><<<g1, TPB, SMEM>>>(i0W0, i0b0, i0W1, i0b1, i0W2, i0b2,
                                      gin, nullptr, f0, nbr_index, nbr_seg, acc, E);

    f1_kernel<<<(VARS * N_PTS * 32 + 255) / 256, 256>>>(f0, acc, nbr_counts);

    int E2 = M_PTS * K_LAST;
    dim3 g2((unsigned)((E2 + TPB - 1) / TPB), VARS);
    edge_kernel<1><<<g2, TPB, SMEM>>>(i1W0, i1b0, i1W1, i1b1, i1W2, i1b2,
                                      gin, gout, f0, nbr_last, nullptr, (float*)d_out, E2);
}